// round 1
// baseline (speedup 1.0000x reference)
#include <cuda_runtime.h>
#include <cuda_bf16.h>
#include <math.h>

// Problem constants
#define T_DIM 2048
#define B_DIM 4
#define K_DIM 512
#define H_DIM 8
#define M_ROWS (T_DIM * B_DIM)          // 8192
#define F_DIM (H_DIM * K_DIM)           // 4096
#define N_HEADS (B_DIM * H_DIM)         // 32
#define ROWSTRIDE_T (B_DIM * F_DIM)     // 16384 : stride between consecutive t for fixed (b,h)

// Scratch (device globals: allocation-free per harness rules)
__device__ float g_q[(size_t)M_ROWS * F_DIM];
__device__ float g_k[(size_t)M_ROWS * F_DIM];
__device__ float g_v[(size_t)M_ROWS * F_DIM];
__device__ float g_s[(size_t)N_HEADS * T_DIM * T_DIM];   // 512 MB scores scratch
__device__ float g_ctx[(size_t)M_ROWS * F_DIM];

// ---------------------------------------------------------------------------
// Generic tiled SGEMM: C = (A @ B [or B^T]) epilogue (optionally +bias, *scale)
// BM=BN=128, BK=16, TM=TN=8, 256 threads.
// Batched via blockIdx.z with element batch-strides.
// ---------------------------------------------------------------------------
#define BM 128
#define BN 128
#define BKK 16
#define TM 8
#define TN 8

template <bool TRANSB, bool HAS_BIAS>
__global__ __launch_bounds__(256, 2)
void sgemm_kernel(int M, int N, int Kd,
                  const float* __restrict__ A, int lda, long long bsA,
                  const float* __restrict__ B, int ldb, long long bsB,
                  float* __restrict__ C, int ldc, long long bsC,
                  const float* __restrict__ bias, float scale)
{
    __shared__ __align__(16) float As[BKK][BM];
    __shared__ __align__(16) float Bs[BKK][BN];

    A += (long long)blockIdx.z * bsA;
    B += (long long)blockIdx.z * bsB;
    C += (long long)blockIdx.z * bsC;

    const int block_row = blockIdx.y * BM;
    const int block_col = blockIdx.x * BN;
    const int tid = threadIdx.x;
    const int tr = tid / (BN / TN);   // 0..15
    const int tc = tid % (BN / TN);   // 0..15

    float acc[TM][TN];
#pragma unroll
    for (int i = 0; i < TM; i++)
#pragma unroll
        for (int j = 0; j < TN; j++) acc[i][j] = 0.f;

    for (int k0 = 0; k0 < Kd; k0 += BKK) {
        // Load A tile (BM x BKK) transposed into As[k][m]
#pragma unroll
        for (int i = tid; i < BM * BKK; i += 256) {
            int m = i / BKK, kk = i % BKK;
            As[kk][m] = A[(long long)(block_row + m) * lda + (k0 + kk)];
        }
        // Load B tile
#pragma unroll
        for (int i = tid; i < BKK * BN; i += 256) {
            if (!TRANSB) {
                int kk = i / BN, n = i % BN;
                Bs[kk][n] = B[(long long)(k0 + kk) * ldb + (block_col + n)];
            } else {
                int n = i / BKK, kk = i % BKK;
                Bs[kk][n] = B[(long long)(block_col + n) * ldb + (k0 + kk)];
            }
        }
        __syncthreads();

#pragma unroll
        for (int kk = 0; kk < BKK; ++kk) {
            float ra[TM], rb[TN];
            const float4* a4 = reinterpret_cast<const float4*>(&As[kk][tr * TM]);
            float4 a0 = a4[0], a1 = a4[1];
            ra[0]=a0.x; ra[1]=a0.y; ra[2]=a0.z; ra[3]=a0.w;
            ra[4]=a1.x; ra[5]=a1.y; ra[6]=a1.z; ra[7]=a1.w;
            const float4* b4 = reinterpret_cast<const float4*>(&Bs[kk][tc * TN]);
            float4 b0 = b4[0], b1 = b4[1];
            rb[0]=b0.x; rb[1]=b0.y; rb[2]=b0.z; rb[3]=b0.w;
            rb[4]=b1.x; rb[5]=b1.y; rb[6]=b1.z; rb[7]=b1.w;
#pragma unroll
            for (int i = 0; i < TM; i++)
#pragma unroll
                for (int j = 0; j < TN; j++)
                    acc[i][j] = fmaf(ra[i], rb[j], acc[i][j]);
        }
        __syncthreads();
    }

#pragma unroll
    for (int i = 0; i < TM; i++) {
        int gm = block_row + tr * TM + i;
#pragma unroll
        for (int j = 0; j < TN; j++) {
            int gn = block_col + tc * TN + j;
            float v = acc[i][j];
            if (HAS_BIAS) v = (v + bias[gn]) * scale;
            C[(long long)gm * ldc + gn] = v;
        }
    }
}

// ---------------------------------------------------------------------------
// Row softmax over 2048 columns; one block (256 thr) per row.
// ---------------------------------------------------------------------------
__global__ __launch_bounds__(256)
void softmax_rows_kernel(float* __restrict__ S)
{
    const int NC = T_DIM;        // 2048
    const int PT = NC / 256;     // 8 per thread
    float* p = S + (size_t)blockIdx.x * NC;
    int tid = threadIdx.x;

    float vals[8];
    float vmax = -INFINITY;
#pragma unroll
    for (int i = 0; i < PT; i++) {
        vals[i] = p[tid + i * 256];
        vmax = fmaxf(vmax, vals[i]);
    }
    __shared__ float red[256];
    red[tid] = vmax; __syncthreads();
    for (int s = 128; s > 0; s >>= 1) {
        if (tid < s) red[tid] = fmaxf(red[tid], red[tid + s]);
        __syncthreads();
    }
    vmax = red[0]; __syncthreads();

    float sum = 0.f;
#pragma unroll
    for (int i = 0; i < PT; i++) {
        vals[i] = __expf(vals[i] - vmax);
        sum += vals[i];
    }
    red[tid] = sum; __syncthreads();
    for (int s = 128; s > 0; s >>= 1) {
        if (tid < s) red[tid] += red[tid + s];
        __syncthreads();
    }
    float inv = 1.f / red[0];
#pragma unroll
    for (int i = 0; i < PT; i++) p[tid + i * 256] = vals[i] * inv;
}

// ---------------------------------------------------------------------------
// Output projection: out[row][o] = sum_f ctx[row][f] * Wo[f][o] + bo[o]
// One block (256 thr) per row; 8 outputs.
// ---------------------------------------------------------------------------
__global__ __launch_bounds__(256)
void out_proj_kernel(const float* __restrict__ ctx, const float* __restrict__ Wo,
                     const float* __restrict__ bo, float* __restrict__ out)
{
    const float* c = ctx + (size_t)blockIdx.x * F_DIM;
    float acc[8] = {0,0,0,0,0,0,0,0};
    for (int f = threadIdx.x; f < F_DIM; f += 256) {
        float cv = c[f];
        const float4* w = reinterpret_cast<const float4*>(Wo + (size_t)f * H_DIM);
        float4 w0 = w[0], w1 = w[1];
        acc[0] = fmaf(cv, w0.x, acc[0]); acc[1] = fmaf(cv, w0.y, acc[1]);
        acc[2] = fmaf(cv, w0.z, acc[2]); acc[3] = fmaf(cv, w0.w, acc[3]);
        acc[4] = fmaf(cv, w1.x, acc[4]); acc[5] = fmaf(cv, w1.y, acc[5]);
        acc[6] = fmaf(cv, w1.z, acc[6]); acc[7] = fmaf(cv, w1.w, acc[7]);
    }
    __shared__ float red[8][256];
#pragma unroll
    for (int o = 0; o < 8; o++) red[o][threadIdx.x] = acc[o];
    __syncthreads();
    for (int s = 128; s > 0; s >>= 1) {
        if (threadIdx.x < s) {
#pragma unroll
            for (int o = 0; o < 8; o++)
                red[o][threadIdx.x] += red[o][threadIdx.x + s];
        }
        __syncthreads();
    }
    if (threadIdx.x < 8)
        out[(size_t)blockIdx.x * H_DIM + threadIdx.x] = red[threadIdx.x][0] + bo[threadIdx.x];
}

// ---------------------------------------------------------------------------
extern "C" void kernel_launch(void* const* d_in, const int* in_sizes, int n_in,
                              void* d_out, int out_size)
{
    const float* x  = (const float*)d_in[0];
    const float* Wq = (const float*)d_in[1];
    const float* bq = (const float*)d_in[2];
    const float* Wk = (const float*)d_in[3];
    const float* bk = (const float*)d_in[4];
    const float* Wv = (const float*)d_in[5];
    const float* bv = (const float*)d_in[6];
    const float* Wo = (const float*)d_in[7];
    const float* bo = (const float*)d_in[8];
    float* out = (float*)d_out;

    float *q, *k, *v, *s, *ctx;
    cudaGetSymbolAddress((void**)&q,   g_q);
    cudaGetSymbolAddress((void**)&k,   g_k);
    cudaGetSymbolAddress((void**)&v,   g_v);
    cudaGetSymbolAddress((void**)&s,   g_s);
    cudaGetSymbolAddress((void**)&ctx, g_ctx);

    const float scale_qk = powf((float)K_DIM, -0.25f);  // applied to q and k each

    // 1) QKV projections: (8192 x 512) @ (512 x 4096) + bias, scaled
    {
        dim3 grid(F_DIM / BN, M_ROWS / BM, 1);  // (32, 64)
        sgemm_kernel<false, true><<<grid, 256>>>(
            M_ROWS, F_DIM, K_DIM, x, K_DIM, 0, Wq, F_DIM, 0, q, F_DIM, 0, bq, scale_qk);
        sgemm_kernel<false, true><<<grid, 256>>>(
            M_ROWS, F_DIM, K_DIM, x, K_DIM, 0, Wk, F_DIM, 0, k, F_DIM, 0, bk, scale_qk);
        sgemm_kernel<false, true><<<grid, 256>>>(
            M_ROWS, F_DIM, K_DIM, x, K_DIM, 0, Wv, F_DIM, 0, v, F_DIM, 0, bv, 1.0f);
    }

    // 2) Scores: per head n, S_n = Q_n @ K_n^T   (2048 x 2048, Kd=512)
    //    Head n=(b*H+h) base offset in q/k = n*K_DIM; t-stride = ROWSTRIDE_T.
    {
        dim3 grid(T_DIM / BN, T_DIM / BM, N_HEADS);  // (16, 16, 32)
        sgemm_kernel<true, false><<<grid, 256>>>(
            T_DIM, T_DIM, K_DIM,
            q, ROWSTRIDE_T, (long long)K_DIM,
            k, ROWSTRIDE_T, (long long)K_DIM,
            s, T_DIM, (long long)T_DIM * T_DIM,
            nullptr, 1.0f);
    }

    // 3) Softmax over last axis: 32*2048 rows of 2048
    softmax_rows_kernel<<<N_HEADS * T_DIM, 256>>>(s);

    // 4) Context: per head n, Ctx_n = P_n @ V_n   (2048 x 512, Kd=2048)
    {
        dim3 grid(K_DIM / BN, T_DIM / BM, N_HEADS);  // (4, 16, 32)
        sgemm_kernel<false, false><<<grid, 256>>>(
            T_DIM, K_DIM, T_DIM,
            s, T_DIM, (long long)T_DIM * T_DIM,
            v, ROWSTRIDE_T, (long long)K_DIM,
            ctx, ROWSTRIDE_T, (long long)K_DIM,
            nullptr, 1.0f);
    }

    // 5) Output projection: (8192 x 4096) @ (4096 x 8) + bo
    out_proj_kernel<<<M_ROWS, 256>>>(ctx, Wo, bo, out);
}

// round 7
// speedup vs baseline: 7.5210x; 7.5210x over previous
#include <cuda_runtime.h>
#include <cuda_bf16.h>
#include <math.h>
#include <stdint.h>

// Problem constants
#define T_DIM 2048
#define B_DIM 4
#define K_DIM 512
#define H_DIM 8
#define M_ROWS (T_DIM * B_DIM)          // 8192
#define F_DIM (H_DIM * K_DIM)           // 4096
#define N_HEADS (B_DIM * H_DIM)         // 32
#define ROWSTRIDE_T (B_DIM * F_DIM)     // 16384

// Scratch (device globals; allocation-free). 256B-aligned for cp.async/float4.
__device__ __align__(256) float g_xr [(size_t)M_ROWS * K_DIM];
__device__ __align__(256) float g_wtq[(size_t)F_DIM * K_DIM];
__device__ __align__(256) float g_wtk[(size_t)F_DIM * K_DIM];
__device__ __align__(256) float g_wtv[(size_t)F_DIM * K_DIM];
__device__ __align__(256) float g_q  [(size_t)M_ROWS * F_DIM];
__device__ __align__(256) float g_k  [(size_t)M_ROWS * F_DIM];
__device__ __align__(256) float g_vt [(size_t)N_HEADS * K_DIM * T_DIM];  // [n][d][t]
__device__ __align__(256) float g_s  [(size_t)N_HEADS * T_DIM * T_DIM]; // scores/probs
__device__ __align__(256) float g_ctx[(size_t)M_ROWS * F_DIM];

// ---------------------------------------------------------------------------
// helpers (base PTX only — no 'a'-suffix features)
// ---------------------------------------------------------------------------
__device__ __forceinline__ float tf32r(float x) {
    float y;
    asm("cvt.rna.tf32.f32 %0, %1;" : "=f"(y) : "f"(x));
    return y;
}
__device__ __forceinline__ uint32_t smem_u32(const void* p) {
    uint32_t a;
    asm("{ .reg .u64 t; cvta.to.shared.u64 t, %1; cvt.u32.u64 %0, t; }" : "=r"(a) : "l"(p));
    return a;
}
__device__ __forceinline__ void cp_async16(uint32_t saddr, const void* gaddr) {
    asm volatile("cp.async.cg.shared.global [%0], [%1], 16;" :: "r"(saddr), "l"(gaddr) : "memory");
}
__device__ __forceinline__ void cp_commit() {
    asm volatile("cp.async.commit_group;" ::: "memory");
}
__device__ __forceinline__ void cp_wait1() {
    asm volatile("cp.async.wait_group 1;" ::: "memory");
}
__device__ __forceinline__ void mma_tf32(float* d, const uint32_t* a, const uint32_t* b) {
    asm volatile(
        "mma.sync.aligned.m16n8k8.row.col.f32.tf32.tf32.f32 "
        "{%0,%1,%2,%3}, {%4,%5,%6,%7}, {%8,%9}, {%0,%1,%2,%3};"
        : "+f"(d[0]), "+f"(d[1]), "+f"(d[2]), "+f"(d[3])
        : "r"(a[0]), "r"(a[1]), "r"(a[2]), "r"(a[3]), "r"(b[0]), "r"(b[1]));
}

// ---------------------------------------------------------------------------
// mma.sync tf32 GEMM: C[m][n] = sum_k A[m][k] * B[n][k]   (both K-major)
// BM=BN=128, BK=32. 256 threads = 8 warps (2x4), warp tile 64x32.
// SMEM rows padded to 36 floats (conflict-free fragment loads).
// Double-buffered cp.async.
// ---------------------------------------------------------------------------
#define PAD_ROW 36
#define TILE_FLOATS (128 * PAD_ROW)          // 4608 per operand tile
#define BUF_FLOATS  (2 * TILE_FLOATS)        // A + B per stage
#define GEMM_SMEM_BYTES (2 * BUF_FLOATS * 4) // 73728

template <bool HAS_BIAS, bool ROUND_OUT, bool TRANS_OUT>
__global__ __launch_bounds__(256)
void mma_gemm(const float* __restrict__ A, int lda, long long bsA,
              const float* __restrict__ B, int ldb, long long bsB,
              float* __restrict__ C, int ldc, long long bsC,
              const float* __restrict__ bias, float scale, int Kd)
{
    extern __shared__ float sm[];
    const uint32_t sbase = smem_u32(sm);

    const int tid = threadIdx.x;
    const int wid = tid >> 5;
    const int lane = tid & 31;
    const int warp_m = wid >> 2;     // 0..1
    const int warp_n = wid & 3;      // 0..3
    const int lr = lane >> 2;        // 0..7
    const int lc = lane & 3;         // 0..3

    A += (long long)blockIdx.z * bsA;
    B += (long long)blockIdx.z * bsB;
    C += (long long)blockIdx.z * bsC;

    const int brow = blockIdx.y * 128;
    const int bcol = blockIdx.x * 128;

    float acc[4][4][4];
#pragma unroll
    for (int mf = 0; mf < 4; mf++)
#pragma unroll
        for (int nf = 0; nf < 4; nf++)
#pragma unroll
            for (int r = 0; r < 4; r++) acc[mf][nf][r] = 0.f;

    const int nch = Kd >> 5;   // chunks of BK=32

    // tile loader: 2048 float4 per chunk (A:1024, B:1024), 8 per thread
    auto load_chunk = [&](int j) {
        const int buf = j & 1;
        const uint32_t abuf = sbase + (uint32_t)(buf * BUF_FLOATS) * 4;
        const uint32_t bbuf = abuf + (uint32_t)TILE_FLOATS * 4;
#pragma unroll
        for (int it = 0; it < 4; it++) {
            int idx = tid + 256 * it;             // A: 0..1023
            int row = idx >> 3, c4 = idx & 7;
            cp_async16(abuf + (uint32_t)(row * PAD_ROW + c4 * 4) * 4,
                       A + (long long)(brow + row) * lda + j * 32 + c4 * 4);
        }
#pragma unroll
        for (int it = 0; it < 4; it++) {
            int idx = tid + 256 * it;             // B: 0..1023
            int row = idx >> 3, c4 = idx & 7;
            cp_async16(bbuf + (uint32_t)(row * PAD_ROW + c4 * 4) * 4,
                       B + (long long)(bcol + row) * ldb + j * 32 + c4 * 4);
        }
    };

    // prologue
    load_chunk(0);
    cp_commit();

    for (int i = 0; i < nch; i++) {
        if (i + 1 < nch) load_chunk(i + 1);
        cp_commit();
        cp_wait1();          // chunk i resident
        __syncthreads();

        const float* Asb = sm + (i & 1) * BUF_FLOATS;
        const float* Bsb = Asb + TILE_FLOATS;

        const int abase = (warp_m * 64 + lr) * PAD_ROW + lc;
        const int bbase = (warp_n * 32 + lr) * PAD_ROW + lc;

#pragma unroll
        for (int ks = 0; ks < 4; ks++) {
            uint32_t af[4][4];
#pragma unroll
            for (int mf = 0; mf < 4; mf++) {
                int p = abase + mf * (16 * PAD_ROW) + ks * 8;
                af[mf][0] = __float_as_uint(Asb[p]);
                af[mf][1] = __float_as_uint(Asb[p + 8 * PAD_ROW]);
                af[mf][2] = __float_as_uint(Asb[p + 4]);
                af[mf][3] = __float_as_uint(Asb[p + 8 * PAD_ROW + 4]);
            }
            uint32_t bf[4][2];
#pragma unroll
            for (int nf = 0; nf < 4; nf++) {
                int p = bbase + nf * (8 * PAD_ROW) + ks * 8;
                bf[nf][0] = __float_as_uint(Bsb[p]);
                bf[nf][1] = __float_as_uint(Bsb[p + 4]);
            }
#pragma unroll
            for (int mf = 0; mf < 4; mf++)
#pragma unroll
                for (int nf = 0; nf < 4; nf++)
                    mma_tf32(acc[mf][nf], af[mf], bf[nf]);
        }
        __syncthreads();     // protect buffer before next-next chunk's loads
    }

    // epilogue: c0: (row=lr, col=2*lc), c1: col+1, c2: row+8, c3: row+8,col+1
#pragma unroll
    for (int mf = 0; mf < 4; mf++) {
        int gm0 = brow + warp_m * 64 + mf * 16 + lr;
#pragma unroll
        for (int nf = 0; nf < 4; nf++) {
            int gn = bcol + warp_n * 32 + nf * 8 + 2 * lc;
#pragma unroll
            for (int half = 0; half < 2; half++) {
                int gm = gm0 + half * 8;
                float v0 = acc[mf][nf][half * 2 + 0];
                float v1 = acc[mf][nf][half * 2 + 1];
                if (HAS_BIAS) {
                    v0 = (v0 + bias[gn]) * scale;
                    v1 = (v1 + bias[gn + 1]) * scale;
                }
                if (ROUND_OUT) { v0 = tf32r(v0); v1 = tf32r(v1); }
                if (!TRANS_OUT) {
                    reinterpret_cast<float2*>(C + (long long)gm * ldc + gn)[0] =
                        make_float2(v0, v1);
                } else {
                    // C = vt[(b*8+h)*512 + d][t], gm=(t*4+b), gn=(h*512+d)
                    int t = gm >> 2, b = gm & 3;
                    int h0 = gn >> 9, d0 = gn & 511;
                    int h1 = (gn + 1) >> 9, d1 = (gn + 1) & 511;
                    C[((size_t)((b << 3) | h0) * 512 + d0) * 2048 + t] = v0;
                    C[((size_t)((b << 3) | h1) * 512 + d1) * 2048 + t] = v1;
                }
            }
        }
    }
}

// ---------------------------------------------------------------------------
// tf32-round x (vectorized elementwise)
// ---------------------------------------------------------------------------
__global__ __launch_bounds__(256)
void round_x_kernel(const float* __restrict__ x, float* __restrict__ xr, int n4)
{
    int i = blockIdx.x * 256 + threadIdx.x;
    if (i < n4) {
        float4 v = reinterpret_cast<const float4*>(x)[i];
        v.x = tf32r(v.x); v.y = tf32r(v.y); v.z = tf32r(v.z); v.w = tf32r(v.w);
        reinterpret_cast<float4*>(xr)[i] = v;
    }
}

// ---------------------------------------------------------------------------
// W (K x F) -> Wt (F x K), tf32 rounded.  block (32,8), grid (F/32, K/32)
// ---------------------------------------------------------------------------
__global__ __launch_bounds__(256)
void transpose_round_kernel(const float* __restrict__ W, float* __restrict__ Wt,
                            int rows, int cols)
{
    __shared__ float tile[32][33];
    int bx = blockIdx.x * 32;   // col base (F)
    int by = blockIdx.y * 32;   // row base (K)
    int tx = threadIdx.x, ty = threadIdx.y;
#pragma unroll
    for (int i = 0; i < 4; i++)
        tile[ty + 8 * i][tx] = W[(size_t)(by + ty + 8 * i) * cols + bx + tx];
    __syncthreads();
#pragma unroll
    for (int i = 0; i < 4; i++)
        Wt[(size_t)(bx + ty + 8 * i) * rows + by + tx] = tf32r(tile[tx][ty + 8 * i]);
}

// ---------------------------------------------------------------------------
// Row softmax over 2048 cols (tf32-rounds probabilities on store)
// ---------------------------------------------------------------------------
__global__ __launch_bounds__(256)
void softmax_rows_kernel(float* __restrict__ S)
{
    const int NC = T_DIM;
    const int PT = NC / 256;
    float* p = S + (size_t)blockIdx.x * NC;
    int tid = threadIdx.x;

    float vals[8];
    float vmax = -INFINITY;
#pragma unroll
    for (int i = 0; i < PT; i++) {
        vals[i] = p[tid + i * 256];
        vmax = fmaxf(vmax, vals[i]);
    }
    __shared__ float red[256];
    red[tid] = vmax; __syncthreads();
    for (int s = 128; s > 0; s >>= 1) {
        if (tid < s) red[tid] = fmaxf(red[tid], red[tid + s]);
        __syncthreads();
    }
    vmax = red[0]; __syncthreads();

    float sum = 0.f;
#pragma unroll
    for (int i = 0; i < PT; i++) {
        vals[i] = __expf(vals[i] - vmax);
        sum += vals[i];
    }
    red[tid] = sum; __syncthreads();
    for (int s = 128; s > 0; s >>= 1) {
        if (tid < s) red[tid] += red[tid + s];
        __syncthreads();
    }
    float inv = 1.f / red[0];
#pragma unroll
    for (int i = 0; i < PT; i++) p[tid + i * 256] = tf32r(vals[i] * inv);
}

// ---------------------------------------------------------------------------
// Output projection (fp32): out[row][o] = sum_f ctx[row][f]*Wo[f][o] + bo[o]
// ---------------------------------------------------------------------------
__global__ __launch_bounds__(256)
void out_proj_kernel(const float* __restrict__ ctx, const float* __restrict__ Wo,
                     const float* __restrict__ bo, float* __restrict__ out)
{
    const float* c = ctx + (size_t)blockIdx.x * F_DIM;
    float acc[8] = {0, 0, 0, 0, 0, 0, 0, 0};
    for (int f = threadIdx.x; f < F_DIM; f += 256) {
        float cv = c[f];
        const float4* w = reinterpret_cast<const float4*>(Wo + (size_t)f * H_DIM);
        float4 w0 = w[0], w1 = w[1];
        acc[0] = fmaf(cv, w0.x, acc[0]); acc[1] = fmaf(cv, w0.y, acc[1]);
        acc[2] = fmaf(cv, w0.z, acc[2]); acc[3] = fmaf(cv, w0.w, acc[3]);
        acc[4] = fmaf(cv, w1.x, acc[4]); acc[5] = fmaf(cv, w1.y, acc[5]);
        acc[6] = fmaf(cv, w1.z, acc[6]); acc[7] = fmaf(cv, w1.w, acc[7]);
    }
    __shared__ float red[8][256];
#pragma unroll
    for (int o = 0; o < 8; o++) red[o][threadIdx.x] = acc[o];
    __syncthreads();
    for (int s = 128; s > 0; s >>= 1) {
        if (threadIdx.x < s) {
#pragma unroll
            for (int o = 0; o < 8; o++)
                red[o][threadIdx.x] += red[o][threadIdx.x + s];
        }
        __syncthreads();
    }
    if (threadIdx.x < 8)
        out[(size_t)blockIdx.x * H_DIM + threadIdx.x] = red[threadIdx.x][0] + bo[threadIdx.x];
}

// ---------------------------------------------------------------------------
extern "C" void kernel_launch(void* const* d_in, const int* in_sizes, int n_in,
                              void* d_out, int out_size)
{
    const float* x  = (const float*)d_in[0];
    const float* Wq = (const float*)d_in[1];
    const float* bq = (const float*)d_in[2];
    const float* Wk = (const float*)d_in[3];
    const float* bk = (const float*)d_in[4];
    const float* Wv = (const float*)d_in[5];
    const float* bv = (const float*)d_in[6];
    const float* Wo = (const float*)d_in[7];
    const float* bo = (const float*)d_in[8];
    float* out = (float*)d_out;

    float *xr, *wtq, *wtk, *wtv, *q, *k, *vt, *s, *ctx;
    cudaGetSymbolAddress((void**)&xr,  g_xr);
    cudaGetSymbolAddress((void**)&wtq, g_wtq);
    cudaGetSymbolAddress((void**)&wtk, g_wtk);
    cudaGetSymbolAddress((void**)&wtv, g_wtv);
    cudaGetSymbolAddress((void**)&q,   g_q);
    cudaGetSymbolAddress((void**)&k,   g_k);
    cudaGetSymbolAddress((void**)&vt,  g_vt);
    cudaGetSymbolAddress((void**)&s,   g_s);
    cudaGetSymbolAddress((void**)&ctx, g_ctx);

    cudaFuncSetAttribute(mma_gemm<true,  true,  false>,
                         cudaFuncAttributeMaxDynamicSharedMemorySize, GEMM_SMEM_BYTES);
    cudaFuncSetAttribute(mma_gemm<true,  true,  true>,
                         cudaFuncAttributeMaxDynamicSharedMemorySize, GEMM_SMEM_BYTES);
    cudaFuncSetAttribute(mma_gemm<false, false, false>,
                         cudaFuncAttributeMaxDynamicSharedMemorySize, GEMM_SMEM_BYTES);

    const float scale_qk = powf((float)K_DIM, -0.25f);

    // 0) tf32-round inputs
    {
        int n4 = M_ROWS * K_DIM / 4;
        round_x_kernel<<<(n4 + 255) / 256, 256>>>(x, xr, n4);
        dim3 tg(F_DIM / 32, K_DIM / 32);
        dim3 tb(32, 8);
        transpose_round_kernel<<<tg, tb>>>(Wq, wtq, K_DIM, F_DIM);
        transpose_round_kernel<<<tg, tb>>>(Wk, wtk, K_DIM, F_DIM);
        transpose_round_kernel<<<tg, tb>>>(Wv, wtv, K_DIM, F_DIM);
    }

    // 1) QKV projections: (8192x512)@(512x4096)  [B = W^T, K-major]
    {
        dim3 grid(F_DIM / 128, M_ROWS / 128, 1);  // (32, 64)
        mma_gemm<true, true, false><<<grid, 256, GEMM_SMEM_BYTES>>>(
            xr, K_DIM, 0, wtq, K_DIM, 0, q, F_DIM, 0, bq, scale_qk, K_DIM);
        mma_gemm<true, true, false><<<grid, 256, GEMM_SMEM_BYTES>>>(
            xr, K_DIM, 0, wtk, K_DIM, 0, k, F_DIM, 0, bk, scale_qk, K_DIM);
        mma_gemm<true, true, true><<<grid, 256, GEMM_SMEM_BYTES>>>(
            xr, K_DIM, 0, wtv, K_DIM, 0, vt, 0, 0, bv, 1.0f, K_DIM);
    }

    // 2) Scores: per head n, S_n = Q_n @ K_n^T  (2048x2048, K=512)
    {
        dim3 grid(T_DIM / 128, T_DIM / 128, N_HEADS);  // (16, 16, 32)
        mma_gemm<false, false, false><<<grid, 256, GEMM_SMEM_BYTES>>>(
            q, ROWSTRIDE_T, (long long)K_DIM,
            k, ROWSTRIDE_T, (long long)K_DIM,
            s, T_DIM, (long long)T_DIM * T_DIM,
            nullptr, 1.0f, K_DIM);
    }

    // 3) Softmax (rounds P to tf32)
    softmax_rows_kernel<<<N_HEADS * T_DIM, 256>>>(s);

    // 4) Context: per head n, Ctx_n = P_n @ V_n  (2048x512, K=2048); B = vt[n]
    {
        dim3 grid(K_DIM / 128, T_DIM / 128, N_HEADS);  // (4, 16, 32)
        mma_gemm<false, false, false><<<grid, 256, GEMM_SMEM_BYTES>>>(
            s, T_DIM, (long long)T_DIM * T_DIM,
            vt, T_DIM, (long long)K_DIM * T_DIM,
            ctx, ROWSTRIDE_T, (long long)K_DIM,
            nullptr, 1.0f, T_DIM);
    }

    // 5) Output projection (fp32, tiny)
    out_proj_kernel<<<M_ROWS, 256>>>(ctx, Wo, bo, out);
}

// round 10
// speedup vs baseline: 7.6734x; 1.0203x over previous
#include <cuda_runtime.h>
#include <cuda_bf16.h>
#include <math.h>
#include <stdint.h>

// Problem constants
#define T_DIM 2048
#define B_DIM 4
#define K_DIM 512
#define H_DIM 8
#define M_ROWS (T_DIM * B_DIM)          // 8192
#define F_DIM (H_DIM * K_DIM)           // 4096
#define N_HEADS (B_DIM * H_DIM)         // 32
#define ROWSTRIDE_T (B_DIM * F_DIM)     // 16384

// Scratch (device globals; allocation-free). 256B-aligned for cp.async/float4.
__device__ __align__(256) float g_xr [(size_t)M_ROWS * K_DIM];
__device__ __align__(256) float g_wtq[(size_t)F_DIM * K_DIM];
__device__ __align__(256) float g_wtk[(size_t)F_DIM * K_DIM];
__device__ __align__(256) float g_wtv[(size_t)F_DIM * K_DIM];
__device__ __align__(256) float g_q  [(size_t)M_ROWS * F_DIM];
__device__ __align__(256) float g_k  [(size_t)M_ROWS * F_DIM];
__device__ __align__(256) float g_vt [(size_t)N_HEADS * K_DIM * T_DIM];  // [n][d][t]
__device__ __align__(256) float g_s  [(size_t)N_HEADS * T_DIM * T_DIM]; // scores/probs
__device__ __align__(256) float g_ctx[(size_t)M_ROWS * F_DIM];

// ---------------------------------------------------------------------------
// helpers (base PTX only — no 'a'-suffix features)
// ---------------------------------------------------------------------------
__device__ __forceinline__ float tf32r(float x) {
    float y;
    asm("cvt.rna.tf32.f32 %0, %1;" : "=f"(y) : "f"(x));
    return y;
}
__device__ __forceinline__ uint32_t smem_u32(const void* p) {
    uint32_t a;
    asm("{ .reg .u64 t; cvta.to.shared.u64 t, %1; cvt.u32.u64 %0, t; }" : "=r"(a) : "l"(p));
    return a;
}
__device__ __forceinline__ void cp_async16(uint32_t saddr, const void* gaddr) {
    asm volatile("cp.async.cg.shared.global [%0], [%1], 16;" :: "r"(saddr), "l"(gaddr) : "memory");
}
__device__ __forceinline__ void cp_commit() {
    asm volatile("cp.async.commit_group;" ::: "memory");
}
__device__ __forceinline__ void cp_wait1() {
    asm volatile("cp.async.wait_group 1;" ::: "memory");
}
__device__ __forceinline__ void mma_tf32(float* d, const uint32_t* a, const uint32_t* b) {
    asm volatile(
        "mma.sync.aligned.m16n8k8.row.col.f32.tf32.tf32.f32 "
        "{%0,%1,%2,%3}, {%4,%5,%6,%7}, {%8,%9}, {%0,%1,%2,%3};"
        : "+f"(d[0]), "+f"(d[1]), "+f"(d[2]), "+f"(d[3])
        : "r"(a[0]), "r"(a[1]), "r"(a[2]), "r"(a[3]), "r"(b[0]), "r"(b[1]));
}

// ---------------------------------------------------------------------------
// mma.sync tf32 GEMM: C[m][n] = sum_k A[m][k] * B[n][k]   (both K-major)
// BM=BN=128, BK=32. 256 threads = 8 warps (2x4), warp tile 64x32.
// SMEM rows padded to 36 floats (conflict-free fragment loads).
// 3-stage cp.async pipeline, ONE __syncthreads per iteration, 2 CTAs/SM.
// ---------------------------------------------------------------------------
#define PAD_ROW 36
#define TILE_FLOATS (128 * PAD_ROW)          // 4608 per operand tile
#define BUF_FLOATS  (2 * TILE_FLOATS)        // A + B per stage (36864 B)
#define N_STAGES 3
#define GEMM_SMEM_BYTES (N_STAGES * BUF_FLOATS * 4) // 110592

template <bool HAS_BIAS, bool ROUND_OUT, bool TRANS_OUT>
__global__ __launch_bounds__(256, 2)
void mma_gemm(const float* __restrict__ A, int lda, long long bsA,
              const float* __restrict__ B, int ldb, long long bsB,
              float* __restrict__ C, int ldc, long long bsC,
              const float* __restrict__ bias, float scale, int Kd)
{
    extern __shared__ float sm[];
    const uint32_t sbase = smem_u32(sm);

    const int tid = threadIdx.x;
    const int wid = tid >> 5;
    const int lane = tid & 31;
    const int warp_m = wid >> 2;     // 0..1
    const int warp_n = wid & 3;      // 0..3
    const int lr = lane >> 2;        // 0..7
    const int lc = lane & 3;         // 0..3

    A += (long long)blockIdx.z * bsA;
    B += (long long)blockIdx.z * bsB;
    C += (long long)blockIdx.z * bsC;

    const int brow = blockIdx.y * 128;
    const int bcol = blockIdx.x * 128;

    float acc[4][4][4];
#pragma unroll
    for (int mf = 0; mf < 4; mf++)
#pragma unroll
        for (int nf = 0; nf < 4; nf++)
#pragma unroll
            for (int r = 0; r < 4; r++) acc[mf][nf][r] = 0.f;

    const int nch = Kd >> 5;   // chunks of BK=32

    // tile loader: 2048 float4 per chunk (A:1024, B:1024), 8 per thread
    auto load_chunk = [&](int j, int stage) {
        const uint32_t abuf = sbase + (uint32_t)(stage * BUF_FLOATS) * 4;
        const uint32_t bbuf = abuf + (uint32_t)TILE_FLOATS * 4;
#pragma unroll
        for (int it = 0; it < 4; it++) {
            int idx = tid + 256 * it;             // A: 0..1023
            int row = idx >> 3, c4 = idx & 7;
            cp_async16(abuf + (uint32_t)(row * PAD_ROW + c4 * 4) * 4,
                       A + (long long)(brow + row) * lda + j * 32 + c4 * 4);
        }
#pragma unroll
        for (int it = 0; it < 4; it++) {
            int idx = tid + 256 * it;             // B: 0..1023
            int row = idx >> 3, c4 = idx & 7;
            cp_async16(bbuf + (uint32_t)(row * PAD_ROW + c4 * 4) * 4,
                       B + (long long)(bcol + row) * ldb + j * 32 + c4 * 4);
        }
    };

    // prologue: chunks 0 and 1 into stages 0, 1
    load_chunk(0, 0);
    cp_commit();
    load_chunk(1, 1);
    cp_commit();

    int stage_c = 0;                 // compute stage = i % 3
    int stage_l = 2;                 // load stage    = (i+2) % 3
    for (int i = 0; i < nch; i++) {
        cp_wait1();          // chunk i resident (this thread; 1 group in flight)
        __syncthreads();     // publishes chunk i to all; proves stage_l (computed
                             // at iter i-1) is free for reuse
        if (i + 2 < nch) load_chunk(i + 2, stage_l);
        cp_commit();         // one group per iteration (possibly empty)

        const float* Asb = sm + stage_c * BUF_FLOATS;
        const float* Bsb = Asb + TILE_FLOATS;

        const int abase = (warp_m * 64 + lr) * PAD_ROW + lc;
        const int bbase = (warp_n * 32 + lr) * PAD_ROW + lc;

#pragma unroll
        for (int ks = 0; ks < 4; ks++) {
            uint32_t af[4][4];
#pragma unroll
            for (int mf = 0; mf < 4; mf++) {
                int p = abase + mf * (16 * PAD_ROW) + ks * 8;
                af[mf][0] = __float_as_uint(Asb[p]);
                af[mf][1] = __float_as_uint(Asb[p + 8 * PAD_ROW]);
                af[mf][2] = __float_as_uint(Asb[p + 4]);
                af[mf][3] = __float_as_uint(Asb[p + 8 * PAD_ROW + 4]);
            }
            uint32_t bf[4][2];
#pragma unroll
            for (int nf = 0; nf < 4; nf++) {
                int p = bbase + nf * (8 * PAD_ROW) + ks * 8;
                bf[nf][0] = __float_as_uint(Bsb[p]);
                bf[nf][1] = __float_as_uint(Bsb[p + 4]);
            }
#pragma unroll
            for (int mf = 0; mf < 4; mf++)
#pragma unroll
                for (int nf = 0; nf < 4; nf++)
                    mma_tf32(acc[mf][nf], af[mf], bf[nf]);
        }

        stage_c = (stage_c == 2) ? 0 : stage_c + 1;
        stage_l = (stage_l == 2) ? 0 : stage_l + 1;
    }

    // epilogue: c0: (row=lr, col=2*lc), c1: col+1, c2: row+8, c3: row+8,col+1
#pragma unroll
    for (int mf = 0; mf < 4; mf++) {
        int gm0 = brow + warp_m * 64 + mf * 16 + lr;
#pragma unroll
        for (int nf = 0; nf < 4; nf++) {
            int gn = bcol + warp_n * 32 + nf * 8 + 2 * lc;
#pragma unroll
            for (int half = 0; half < 2; half++) {
                int gm = gm0 + half * 8;
                float v0 = acc[mf][nf][half * 2 + 0];
                float v1 = acc[mf][nf][half * 2 + 1];
                if (HAS_BIAS) {
                    v0 = (v0 + bias[gn]) * scale;
                    v1 = (v1 + bias[gn + 1]) * scale;
                }
                if (ROUND_OUT) { v0 = tf32r(v0); v1 = tf32r(v1); }
                if (!TRANS_OUT) {
                    reinterpret_cast<float2*>(C + (long long)gm * ldc + gn)[0] =
                        make_float2(v0, v1);
                } else {
                    // C = vt[(b*8+h)*512 + d][t], gm=(t*4+b), gn=(h*512+d)
                    int t = gm >> 2, b = gm & 3;
                    int h0 = gn >> 9, d0 = gn & 511;
                    int h1 = (gn + 1) >> 9, d1 = (gn + 1) & 511;
                    C[((size_t)((b << 3) | h0) * 512 + d0) * 2048 + t] = v0;
                    C[((size_t)((b << 3) | h1) * 512 + d1) * 2048 + t] = v1;
                }
            }
        }
    }
}

// ---------------------------------------------------------------------------
// tf32-round x (vectorized elementwise)
// ---------------------------------------------------------------------------
__global__ __launch_bounds__(256)
void round_x_kernel(const float* __restrict__ x, float* __restrict__ xr, int n4)
{
    int i = blockIdx.x * 256 + threadIdx.x;
    if (i < n4) {
        float4 v = reinterpret_cast<const float4*>(x)[i];
        v.x = tf32r(v.x); v.y = tf32r(v.y); v.z = tf32r(v.z); v.w = tf32r(v.w);
        reinterpret_cast<float4*>(xr)[i] = v;
    }
}

// ---------------------------------------------------------------------------
// W (K x F) -> Wt (F x K), tf32 rounded.  block (32,8), grid (F/32, K/32)
// ---------------------------------------------------------------------------
__global__ __launch_bounds__(256)
void transpose_round_kernel(const float* __restrict__ W, float* __restrict__ Wt,
                            int rows, int cols)
{
    __shared__ float tile[32][33];
    int bx = blockIdx.x * 32;   // col base (F)
    int by = blockIdx.y * 32;   // row base (K)
    int tx = threadIdx.x, ty = threadIdx.y;
#pragma unroll
    for (int i = 0; i < 4; i++)
        tile[ty + 8 * i][tx] = W[(size_t)(by + ty + 8 * i) * cols + bx + tx];
    __syncthreads();
#pragma unroll
    for (int i = 0; i < 4; i++)
        Wt[(size_t)(bx + ty + 8 * i) * rows + by + tx] = tf32r(tile[tx][ty + 8 * i]);
}

// ---------------------------------------------------------------------------
// Row softmax over 2048 cols (tf32-rounds probabilities on store)
// ---------------------------------------------------------------------------
__global__ __launch_bounds__(256)
void softmax_rows_kernel(float* __restrict__ S)
{
    const int NC = T_DIM;
    const int PT = NC / 256;
    float* p = S + (size_t)blockIdx.x * NC;
    int tid = threadIdx.x;

    float vals[8];
    float vmax = -INFINITY;
#pragma unroll
    for (int i = 0; i < PT; i++) {
        vals[i] = p[tid + i * 256];
        vmax = fmaxf(vmax, vals[i]);
    }
    __shared__ float red[256];
    red[tid] = vmax; __syncthreads();
    for (int s = 128; s > 0; s >>= 1) {
        if (tid < s) red[tid] = fmaxf(red[tid], red[tid + s]);
        __syncthreads();
    }
    vmax = red[0]; __syncthreads();

    float sum = 0.f;
#pragma unroll
    for (int i = 0; i < PT; i++) {
        vals[i] = __expf(vals[i] - vmax);
        sum += vals[i];
    }
    red[tid] = sum; __syncthreads();
    for (int s = 128; s > 0; s >>= 1) {
        if (tid < s) red[tid] += red[tid + s];
        __syncthreads();
    }
    float inv = 1.f / red[0];
#pragma unroll
    for (int i = 0; i < PT; i++) p[tid + i * 256] = tf32r(vals[i] * inv);
}

// ---------------------------------------------------------------------------
// Output projection (fp32): out[row][o] = sum_f ctx[row][f]*Wo[f][o] + bo[o]
// ---------------------------------------------------------------------------
__global__ __launch_bounds__(256)
void out_proj_kernel(const float* __restrict__ ctx, const float* __restrict__ Wo,
                     const float* __restrict__ bo, float* __restrict__ out)
{
    const float* c = ctx + (size_t)blockIdx.x * F_DIM;
    float acc[8] = {0, 0, 0, 0, 0, 0, 0, 0};
    for (int f = threadIdx.x; f < F_DIM; f += 256) {
        float cv = c[f];
        const float4* w = reinterpret_cast<const float4*>(Wo + (size_t)f * H_DIM);
        float4 w0 = w[0], w1 = w[1];
        acc[0] = fmaf(cv, w0.x, acc[0]); acc[1] = fmaf(cv, w0.y, acc[1]);
        acc[2] = fmaf(cv, w0.z, acc[2]); acc[3] = fmaf(cv, w0.w, acc[3]);
        acc[4] = fmaf(cv, w1.x, acc[4]); acc[5] = fmaf(cv, w1.y, acc[5]);
        acc[6] = fmaf(cv, w1.z, acc[6]); acc[7] = fmaf(cv, w1.w, acc[7]);
    }
    __shared__ float red[8][256];
#pragma unroll
    for (int o = 0; o < 8; o++) red[o][threadIdx.x] = acc[o];
    __syncthreads();
    for (int s = 128; s > 0; s >>= 1) {
        if (threadIdx.x < s) {
#pragma unroll
            for (int o = 0; o < 8; o++)
                red[o][threadIdx.x] += red[o][threadIdx.x + s];
        }
        __syncthreads();
    }
    if (threadIdx.x < 8)
        out[(size_t)blockIdx.x * H_DIM + threadIdx.x] = red[threadIdx.x][0] + bo[threadIdx.x];
}

// ---------------------------------------------------------------------------
extern "C" void kernel_launch(void* const* d_in, const int* in_sizes, int n_in,
                              void* d_out, int out_size)
{
    const float* x  = (const float*)d_in[0];
    const float* Wq = (const float*)d_in[1];
    const float* bq = (const float*)d_in[2];
    const float* Wk = (const float*)d_in[3];
    const float* bk = (const float*)d_in[4];
    const float* Wv = (const float*)d_in[5];
    const float* bv = (const float*)d_in[6];
    const float* Wo = (const float*)d_in[7];
    const float* bo = (const float*)d_in[8];
    float* out = (float*)d_out;

    float *xr, *wtq, *wtk, *wtv, *q, *k, *vt, *s, *ctx;
    cudaGetSymbolAddress((void**)&xr,  g_xr);
    cudaGetSymbolAddress((void**)&wtq, g_wtq);
    cudaGetSymbolAddress((void**)&wtk, g_wtk);
    cudaGetSymbolAddress((void**)&wtv, g_wtv);
    cudaGetSymbolAddress((void**)&q,   g_q);
    cudaGetSymbolAddress((void**)&k,   g_k);
    cudaGetSymbolAddress((void**)&vt,  g_vt);
    cudaGetSymbolAddress((void**)&s,   g_s);
    cudaGetSymbolAddress((void**)&ctx, g_ctx);

    cudaFuncSetAttribute(mma_gemm<true,  true,  false>,
                         cudaFuncAttributeMaxDynamicSharedMemorySize, GEMM_SMEM_BYTES);
    cudaFuncSetAttribute(mma_gemm<true,  true,  true>,
                         cudaFuncAttributeMaxDynamicSharedMemorySize, GEMM_SMEM_BYTES);
    cudaFuncSetAttribute(mma_gemm<false, false, false>,
                         cudaFuncAttributeMaxDynamicSharedMemorySize, GEMM_SMEM_BYTES);

    const float scale_qk = powf((float)K_DIM, -0.25f);

    // 0) tf32-round inputs
    {
        int n4 = M_ROWS * K_DIM / 4;
        round_x_kernel<<<(n4 + 255) / 256, 256>>>(x, xr, n4);
        dim3 tg(F_DIM / 32, K_DIM / 32);
        dim3 tb(32, 8);
        transpose_round_kernel<<<tg, tb>>>(Wq, wtq, K_DIM, F_DIM);
        transpose_round_kernel<<<tg, tb>>>(Wk, wtk, K_DIM, F_DIM);
        transpose_round_kernel<<<tg, tb>>>(Wv, wtv, K_DIM, F_DIM);
    }

    // 1) QKV projections: (8192x512)@(512x4096)  [B = W^T, K-major]
    {
        dim3 grid(F_DIM / 128, M_ROWS / 128, 1);  // (32, 64)
        mma_gemm<true, true, false><<<grid, 256, GEMM_SMEM_BYTES>>>(
            xr, K_DIM, 0, wtq, K_DIM, 0, q, F_DIM, 0, bq, scale_qk, K_DIM);
        mma_gemm<true, true, false><<<grid, 256, GEMM_SMEM_BYTES>>>(
            xr, K_DIM, 0, wtk, K_DIM, 0, k, F_DIM, 0, bk, scale_qk, K_DIM);
        mma_gemm<true, true, true><<<grid, 256, GEMM_SMEM_BYTES>>>(
            xr, K_DIM, 0, wtv, K_DIM, 0, vt, 0, 0, bv, 1.0f, K_DIM);
    }

    // 2) Scores: per head n, S_n = Q_n @ K_n^T  (2048x2048, K=512)
    {
        dim3 grid(T_DIM / 128, T_DIM / 128, N_HEADS);  // (16, 16, 32)
        mma_gemm<false, false, false><<<grid, 256, GEMM_SMEM_BYTES>>>(
            q, ROWSTRIDE_T, (long long)K_DIM,
            k, ROWSTRIDE_T, (long long)K_DIM,
            s, T_DIM, (long long)T_DIM * T_DIM,
            nullptr, 1.0f, K_DIM);
    }

    // 3) Softmax (rounds P to tf32)
    softmax_rows_kernel<<<N_HEADS * T_DIM, 256>>>(s);

    // 4) Context: per head n, Ctx_n = P_n @ V_n  (2048x512, K=2048); B = vt[n]
    {
        dim3 grid(K_DIM / 128, T_DIM / 128, N_HEADS);  // (4, 16, 32)
        mma_gemm<false, false, false><<<grid, 256, GEMM_SMEM_BYTES>>>(
            s, T_DIM, (long long)T_DIM * T_DIM,
            vt, T_DIM, (long long)K_DIM * T_DIM,
            ctx, ROWSTRIDE_T, (long long)K_DIM,
            nullptr, 1.0f, T_DIM);
    }

    // 5) Output projection (fp32, tiny)
    out_proj_kernel<<<M_ROWS, 256>>>(ctx, Wo, bo, out);
}

// round 16
// speedup vs baseline: 12.0857x; 1.5750x over previous
#include <cuda_runtime.h>
#include <cuda_fp16.h>
#include <math.h>
#include <stdint.h>

// Problem constants
#define T_DIM 2048
#define B_DIM 4
#define K_DIM 512
#define H_DIM 8
#define M_ROWS (T_DIM * B_DIM)          // 8192
#define F_DIM (H_DIM * K_DIM)           // 4096
#define N_HEADS (B_DIM * H_DIM)         // 32
#define ROWSTRIDE_T (B_DIM * F_DIM)     // 16384

// Scratch (device globals; allocation-free). 256B-aligned.
__device__ __align__(256) __half g_xh [(size_t)M_ROWS * K_DIM];
__device__ __align__(256) __half g_wtq[(size_t)F_DIM * K_DIM];
__device__ __align__(256) __half g_wtk[(size_t)F_DIM * K_DIM];
__device__ __align__(256) __half g_wtv[(size_t)F_DIM * K_DIM];
__device__ __align__(256) __half g_qh [(size_t)M_ROWS * F_DIM];
__device__ __align__(256) __half g_kh [(size_t)M_ROWS * F_DIM];
__device__ __align__(256) __half g_vt [(size_t)N_HEADS * K_DIM * T_DIM]; // [n][d][t]
__device__ __align__(256) float  g_s  [(size_t)N_HEADS * T_DIM * T_DIM]; // fp32 scores
__device__ __align__(256) __half g_p  [(size_t)N_HEADS * T_DIM * T_DIM]; // fp16 probs
__device__ __align__(256) float  g_ctx[(size_t)M_ROWS * F_DIM];

// ---------------------------------------------------------------------------
// helpers (base PTX only)
// ---------------------------------------------------------------------------
__device__ __forceinline__ uint32_t smem_u32(const void* p) {
    uint32_t a;
    asm("{ .reg .u64 t; cvta.to.shared.u64 t, %1; cvt.u32.u64 %0, t; }" : "=r"(a) : "l"(p));
    return a;
}
__device__ __forceinline__ void cp_async16(uint32_t saddr, const void* gaddr) {
    asm volatile("cp.async.cg.shared.global [%0], [%1], 16;" :: "r"(saddr), "l"(gaddr) : "memory");
}
__device__ __forceinline__ void cp_commit() {
    asm volatile("cp.async.commit_group;" ::: "memory");
}
__device__ __forceinline__ void cp_wait1() {
    asm volatile("cp.async.wait_group 1;" ::: "memory");
}
__device__ __forceinline__ void mma_f16(float* d, const uint32_t* a, const uint32_t* b) {
    asm volatile(
        "mma.sync.aligned.m16n8k16.row.col.f32.f16.f16.f32 "
        "{%0,%1,%2,%3}, {%4,%5,%6,%7}, {%8,%9}, {%0,%1,%2,%3};"
        : "+f"(d[0]), "+f"(d[1]), "+f"(d[2]), "+f"(d[3])
        : "r"(a[0]), "r"(a[1]), "r"(a[2]), "r"(a[3]), "r"(b[0]), "r"(b[1]));
}

// ---------------------------------------------------------------------------
// mma.sync fp16 GEMM: C[m][n] = sum_k A[m][k] * B[n][k]  (both K-major, half)
// BM=BN=128, BK=32 (2 k16 steps). 8 warps (2x4), warp tile 64x32.
// SMEM rows padded to 40 halves (conflict-free fragment loads).
// 3-stage cp.async pipeline, one __syncthreads per iteration, 2 CTAs/SM.
// ---------------------------------------------------------------------------
#define PAD_ROW_H 40
#define TILE_HALF (128 * PAD_ROW_H)          // 5120 halves = 10240 B
#define BUF_HALF  (2 * TILE_HALF)            // A + B per stage (20480 B)
#define N_STAGES 3
#define GEMM_SMEM_BYTES (N_STAGES * BUF_HALF * 2)  // 61440

template <typename TC, bool HAS_BIAS, bool TRANS_OUT>
__global__ __launch_bounds__(256, 2)
void mma_gemm(const __half* __restrict__ A, int lda, long long bsA,
              const __half* __restrict__ B, int ldb, long long bsB,
              TC* __restrict__ C, int ldc, long long bsC,
              const float* __restrict__ bias, float scale, int Kd)
{
    extern __shared__ __half smh[];
    const uint32_t sbase = smem_u32(smh);

    const int tid = threadIdx.x;
    const int wid = tid >> 5;
    const int lane = tid & 31;
    const int warp_m = wid >> 2;     // 0..1
    const int warp_n = wid & 3;      // 0..3
    const int lr = lane >> 2;        // 0..7  (groupID)
    const int lc = lane & 3;         // 0..3  (threadID_in_group)

    A += (long long)blockIdx.z * bsA;
    B += (long long)blockIdx.z * bsB;
    C += (long long)blockIdx.z * bsC;

    const int brow = blockIdx.y * 128;
    const int bcol = blockIdx.x * 128;

    float acc[4][4][4];
#pragma unroll
    for (int mf = 0; mf < 4; mf++)
#pragma unroll
        for (int nf = 0; nf < 4; nf++)
#pragma unroll
            for (int r = 0; r < 4; r++) acc[mf][nf][r] = 0.f;

    const int nch = Kd >> 5;   // chunks of BK=32

    // loader: per chunk, A tile 128x32 halves + B tile 128x32 halves.
    auto load_chunk = [&](int j, int stage) {
        const uint32_t abuf = sbase + (uint32_t)(stage * BUF_HALF) * 2;
        const uint32_t bbuf = abuf + (uint32_t)TILE_HALF * 2;
#pragma unroll
        for (int it = 0; it < 2; it++) {
            int idx = tid + 256 * it;             // 0..511
            int row = idx >> 2, c8 = idx & 3;
            cp_async16(abuf + (uint32_t)(row * (PAD_ROW_H * 2) + c8 * 16),
                       A + (long long)(brow + row) * lda + j * 32 + c8 * 8);
        }
#pragma unroll
        for (int it = 0; it < 2; it++) {
            int idx = tid + 256 * it;             // 0..511
            int row = idx >> 2, c8 = idx & 3;
            cp_async16(bbuf + (uint32_t)(row * (PAD_ROW_H * 2) + c8 * 16),
                       B + (long long)(bcol + row) * ldb + j * 32 + c8 * 8);
        }
    };

    // prologue: chunks 0, 1 -> stages 0, 1
    load_chunk(0, 0);
    cp_commit();
    load_chunk(1, 1);
    cp_commit();

    int stage_c = 0;
    int stage_l = 2;
    for (int i = 0; i < nch; i++) {
        cp_wait1();          // chunk i resident (this thread)
        __syncthreads();     // publish chunk i; stage_l proven free
        if (i + 2 < nch) load_chunk(i + 2, stage_l);
        cp_commit();         // one group per iteration (possibly empty)

        const __half* Asb = smh + stage_c * BUF_HALF;
        const __half* Bsb = Asb + TILE_HALF;

        const int arow = (warp_m * 64 + lr) * PAD_ROW_H;
        const int brow_s = (warp_n * 32 + lr) * PAD_ROW_H;

#pragma unroll
        for (int ks = 0; ks < 2; ks++) {
            const int koff = ks * 16 + 2 * lc;
            uint32_t af[4][4];
#pragma unroll
            for (int mf = 0; mf < 4; mf++) {
                int p = arow + mf * (16 * PAD_ROW_H) + koff;
                af[mf][0] = *reinterpret_cast<const uint32_t*>(Asb + p);
                af[mf][1] = *reinterpret_cast<const uint32_t*>(Asb + p + 8 * PAD_ROW_H);
                af[mf][2] = *reinterpret_cast<const uint32_t*>(Asb + p + 8);
                af[mf][3] = *reinterpret_cast<const uint32_t*>(Asb + p + 8 * PAD_ROW_H + 8);
            }
            uint32_t bf[4][2];
#pragma unroll
            for (int nf = 0; nf < 4; nf++) {
                int p = brow_s + nf * (8 * PAD_ROW_H) + koff;
                bf[nf][0] = *reinterpret_cast<const uint32_t*>(Bsb + p);
                bf[nf][1] = *reinterpret_cast<const uint32_t*>(Bsb + p + 8);
            }
#pragma unroll
            for (int mf = 0; mf < 4; mf++)
#pragma unroll
                for (int nf = 0; nf < 4; nf++)
                    mma_f16(acc[mf][nf], af[mf], bf[nf]);
        }

        stage_c = (stage_c == 2) ? 0 : stage_c + 1;
        stage_l = (stage_l == 2) ? 0 : stage_l + 1;
    }

    // epilogue: c0/c1 = (lr, 2lc/2lc+1), c2/c3 = (lr+8, same cols)
#pragma unroll
    for (int mf = 0; mf < 4; mf++) {
        int gm0 = brow + warp_m * 64 + mf * 16 + lr;
#pragma unroll
        for (int nf = 0; nf < 4; nf++) {
            int gn = bcol + warp_n * 32 + nf * 8 + 2 * lc;
#pragma unroll
            for (int half_i = 0; half_i < 2; half_i++) {
                int gm = gm0 + half_i * 8;
                float v0 = acc[mf][nf][half_i * 2 + 0];
                float v1 = acc[mf][nf][half_i * 2 + 1];
                if (HAS_BIAS) {
                    v0 = (v0 + bias[gn]) * scale;
                    v1 = (v1 + bias[gn + 1]) * scale;
                }
                if (!TRANS_OUT) {
                    if (sizeof(TC) == 2) {
                        __half2 h = __floats2half2_rn(v0, v1);
                        *reinterpret_cast<__half2*>(
                            reinterpret_cast<__half*>(C) + (long long)gm * ldc + gn) = h;
                    } else {
                        *reinterpret_cast<float2*>(
                            reinterpret_cast<float*>(C) + (long long)gm * ldc + gn) =
                            make_float2(v0, v1);
                    }
                } else {
                    // C = vt[(b*8+h)*512 + d][t] (half), gm=(t*4+b), gn=(h*512+d)
                    int t = gm >> 2, b = gm & 3;
                    int h0 = gn >> 9, d0 = gn & 511;
                    int h1 = (gn + 1) >> 9, d1 = (gn + 1) & 511;
                    __half* Ch = reinterpret_cast<__half*>(C);
                    Ch[((size_t)((b << 3) | h0) * 512 + d0) * 2048 + t] = __float2half_rn(v0);
                    Ch[((size_t)((b << 3) | h1) * 512 + d1) * 2048 + t] = __float2half_rn(v1);
                }
            }
        }
    }
}

// ---------------------------------------------------------------------------
// x (float) -> half
// ---------------------------------------------------------------------------
__global__ __launch_bounds__(256)
void convert_x_kernel(const float* __restrict__ x, __half* __restrict__ xh, int n4)
{
    int i = blockIdx.x * 256 + threadIdx.x;
    if (i < n4) {
        float4 v = reinterpret_cast<const float4*>(x)[i];
        reinterpret_cast<__half2*>(xh)[2 * i]     = __floats2half2_rn(v.x, v.y);
        reinterpret_cast<__half2*>(xh)[2 * i + 1] = __floats2half2_rn(v.z, v.w);
    }
}

// ---------------------------------------------------------------------------
// W (K x F, float) -> Wt (F x K, half).  block (32,8), grid (F/32, K/32)
// ---------------------------------------------------------------------------
__global__ __launch_bounds__(256)
void transpose_half_kernel(const float* __restrict__ W, __half* __restrict__ Wt,
                           int rows, int cols)
{
    __shared__ float tile[32][33];
    int bx = blockIdx.x * 32;   // col base (F)
    int by = blockIdx.y * 32;   // row base (K)
    int tx = threadIdx.x, ty = threadIdx.y;
#pragma unroll
    for (int i = 0; i < 4; i++)
        tile[ty + 8 * i][tx] = W[(size_t)(by + ty + 8 * i) * cols + bx + tx];
    __syncthreads();
#pragma unroll
    for (int i = 0; i < 4; i++)
        Wt[(size_t)(bx + ty + 8 * i) * rows + by + tx] =
            __float2half_rn(tile[tx][ty + 8 * i]);
}

// ---------------------------------------------------------------------------
// Row softmax over 2048 cols: fp32 scores in, fp16 probs out
// ---------------------------------------------------------------------------
__global__ __launch_bounds__(256)
void softmax_rows_kernel(const float* __restrict__ S, __half* __restrict__ P)
{
    const int NC = T_DIM;
    const int PT = NC / 256;
    const float* p = S + (size_t)blockIdx.x * NC;
    __half* q = P + (size_t)blockIdx.x * NC;
    int tid = threadIdx.x;

    float vals[8];
    float vmax = -INFINITY;
#pragma unroll
    for (int i = 0; i < PT; i++) {
        vals[i] = p[tid + i * 256];
        vmax = fmaxf(vmax, vals[i]);
    }
    __shared__ float red[256];
    red[tid] = vmax; __syncthreads();
    for (int s = 128; s > 0; s >>= 1) {
        if (tid < s) red[tid] = fmaxf(red[tid], red[tid + s]);
        __syncthreads();
    }
    vmax = red[0]; __syncthreads();

    float sum = 0.f;
#pragma unroll
    for (int i = 0; i < PT; i++) {
        vals[i] = __expf(vals[i] - vmax);
        sum += vals[i];
    }
    red[tid] = sum; __syncthreads();
    for (int s = 128; s > 0; s >>= 1) {
        if (tid < s) red[tid] += red[tid + s];
        __syncthreads();
    }
    float inv = 1.f / red[0];
#pragma unroll
    for (int i = 0; i < PT; i++) q[tid + i * 256] = __float2half_rn(vals[i] * inv);
}

// ---------------------------------------------------------------------------
// Output projection (fp32): out[row][o] = sum_f ctx[row][f]*Wo[f][o] + bo[o]
// ---------------------------------------------------------------------------
__global__ __launch_bounds__(256)
void out_proj_kernel(const float* __restrict__ ctx, const float* __restrict__ Wo,
                     const float* __restrict__ bo, float* __restrict__ out)
{
    const float* c = ctx + (size_t)blockIdx.x * F_DIM;
    float acc[8] = {0, 0, 0, 0, 0, 0, 0, 0};
    for (int f = threadIdx.x; f < F_DIM; f += 256) {
        float cv = c[f];
        const float4* w = reinterpret_cast<const float4*>(Wo + (size_t)f * H_DIM);
        float4 w0 = w[0], w1 = w[1];
        acc[0] = fmaf(cv, w0.x, acc[0]); acc[1] = fmaf(cv, w0.y, acc[1]);
        acc[2] = fmaf(cv, w0.z, acc[2]); acc[3] = fmaf(cv, w0.w, acc[3]);
        acc[4] = fmaf(cv, w1.x, acc[4]); acc[5] = fmaf(cv, w1.y, acc[5]);
        acc[6] = fmaf(cv, w1.z, acc[6]); acc[7] = fmaf(cv, w1.w, acc[7]);
    }
    __shared__ float red[8][256];
#pragma unroll
    for (int o = 0; o < 8; o++) red[o][threadIdx.x] = acc[o];
    __syncthreads();
    for (int s = 128; s > 0; s >>= 1) {
        if (threadIdx.x < s) {
#pragma unroll
            for (int o = 0; o < 8; o++)
                red[o][threadIdx.x] += red[o][threadIdx.x + s];
        }
        __syncthreads();
    }
    if (threadIdx.x < 8)
        out[(size_t)blockIdx.x * H_DIM + threadIdx.x] = red[threadIdx.x][0] + bo[threadIdx.x];
}

// ---------------------------------------------------------------------------
extern "C" void kernel_launch(void* const* d_in, const int* in_sizes, int n_in,
                              void* d_out, int out_size)
{
    const float* x  = (const float*)d_in[0];
    const float* Wq = (const float*)d_in[1];
    const float* bq = (const float*)d_in[2];
    const float* Wk = (const float*)d_in[3];
    const float* bk = (const float*)d_in[4];
    const float* Wv = (const float*)d_in[5];
    const float* bv = (const float*)d_in[6];
    const float* Wo = (const float*)d_in[7];
    const float* bo = (const float*)d_in[8];
    float* out = (float*)d_out;

    __half *xh, *wtq, *wtk, *wtv, *qh, *kh, *vt, *pp;
    float *s, *ctx;
    cudaGetSymbolAddress((void**)&xh,  g_xh);
    cudaGetSymbolAddress((void**)&wtq, g_wtq);
    cudaGetSymbolAddress((void**)&wtk, g_wtk);
    cudaGetSymbolAddress((void**)&wtv, g_wtv);
    cudaGetSymbolAddress((void**)&qh,  g_qh);
    cudaGetSymbolAddress((void**)&kh,  g_kh);
    cudaGetSymbolAddress((void**)&vt,  g_vt);
    cudaGetSymbolAddress((void**)&s,   g_s);
    cudaGetSymbolAddress((void**)&pp,  g_p);
    cudaGetSymbolAddress((void**)&ctx, g_ctx);

    cudaFuncSetAttribute(mma_gemm<__half, true,  false>,
                         cudaFuncAttributeMaxDynamicSharedMemorySize, GEMM_SMEM_BYTES);
    cudaFuncSetAttribute(mma_gemm<__half, true,  true>,
                         cudaFuncAttributeMaxDynamicSharedMemorySize, GEMM_SMEM_BYTES);
    cudaFuncSetAttribute(mma_gemm<float,  false, false>,
                         cudaFuncAttributeMaxDynamicSharedMemorySize, GEMM_SMEM_BYTES);

    const float scale_qk = powf((float)K_DIM, -0.25f);

    // 0) convert inputs to half
    {
        int n4 = M_ROWS * K_DIM / 4;
        convert_x_kernel<<<(n4 + 255) / 256, 256>>>(x, xh, n4);
        dim3 tg(F_DIM / 32, K_DIM / 32);
        dim3 tb(32, 8);
        transpose_half_kernel<<<tg, tb>>>(Wq, wtq, K_DIM, F_DIM);
        transpose_half_kernel<<<tg, tb>>>(Wk, wtk, K_DIM, F_DIM);
        transpose_half_kernel<<<tg, tb>>>(Wv, wtv, K_DIM, F_DIM);
    }

    // 1) QKV projections: (8192x512)@(512x4096)
    {
        dim3 grid(F_DIM / 128, M_ROWS / 128, 1);  // (32, 64)
        mma_gemm<__half, true, false><<<grid, 256, GEMM_SMEM_BYTES>>>(
            xh, K_DIM, 0, wtq, K_DIM, 0, qh, F_DIM, 0, bq, scale_qk, K_DIM);
        mma_gemm<__half, true, false><<<grid, 256, GEMM_SMEM_BYTES>>>(
            xh, K_DIM, 0, wtk, K_DIM, 0, kh, F_DIM, 0, bk, scale_qk, K_DIM);
        mma_gemm<__half, true, true><<<grid, 256, GEMM_SMEM_BYTES>>>(
            xh, K_DIM, 0, wtv, K_DIM, 0, vt, 0, 0, bv, 1.0f, K_DIM);
    }

    // 2) Scores: per head n, S_n = Q_n @ K_n^T  (2048x2048, K=512), fp32 out
    {
        dim3 grid(T_DIM / 128, T_DIM / 128, N_HEADS);  // (16, 16, 32)
        mma_gemm<float, false, false><<<grid, 256, GEMM_SMEM_BYTES>>>(
            qh, ROWSTRIDE_T, (long long)K_DIM,
            kh, ROWSTRIDE_T, (long long)K_DIM,
            s, T_DIM, (long long)T_DIM * T_DIM,
            nullptr, 1.0f, K_DIM);
    }

    // 3) Softmax: fp32 scores -> fp16 probs
    softmax_rows_kernel<<<N_HEADS * T_DIM, 256>>>(s, pp);

    // 4) Context: per head n, Ctx_n = P_n @ V_n  (2048x512, K=2048), fp32 out
    {
        dim3 grid(K_DIM / 128, T_DIM / 128, N_HEADS);  // (4, 16, 32)
        mma_gemm<float, false, false><<<grid, 256, GEMM_SMEM_BYTES>>>(
            pp, T_DIM, (long long)T_DIM * T_DIM,
            vt, T_DIM, (long long)K_DIM * T_DIM,
            ctx, ROWSTRIDE_T, (long long)K_DIM,
            nullptr, 1.0f, T_DIM);
    }

    // 5) Output projection (fp32, tiny)
    out_proj_kernel<<<M_ROWS, 256>>>(ctx, Wo, bo, out);
}

// round 17
// speedup vs baseline: 13.3002x; 1.1005x over previous
#include <cuda_runtime.h>
#include <cuda_fp16.h>
#include <math.h>
#include <stdint.h>

// Problem constants
#define T_DIM 2048
#define B_DIM 4
#define K_DIM 512
#define H_DIM 8
#define M_ROWS (T_DIM * B_DIM)          // 8192
#define F_DIM (H_DIM * K_DIM)           // 4096
#define N_HEADS (B_DIM * H_DIM)         // 32
#define ROWSTRIDE_T (B_DIM * F_DIM)     // 16384

// Scratch (device globals; allocation-free). 256B-aligned.
__device__ __align__(256) __half g_xh [(size_t)M_ROWS * K_DIM];
__device__ __align__(256) __half g_wtq[(size_t)F_DIM * K_DIM];
__device__ __align__(256) __half g_wtk[(size_t)F_DIM * K_DIM];
__device__ __align__(256) __half g_wtv[(size_t)F_DIM * K_DIM];
__device__ __align__(256) __half g_qh [(size_t)M_ROWS * F_DIM];
__device__ __align__(256) __half g_kh [(size_t)M_ROWS * F_DIM];
__device__ __align__(256) __half g_vt [(size_t)N_HEADS * K_DIM * T_DIM]; // [n][d][t]
__device__ __align__(256) float  g_s  [(size_t)N_HEADS * T_DIM * T_DIM]; // fp32 scores
__device__ __align__(256) __half g_p  [(size_t)N_HEADS * T_DIM * T_DIM]; // fp16 probs
__device__ __align__(256) float  g_ctx[(size_t)M_ROWS * F_DIM];

// ---------------------------------------------------------------------------
// helpers (base PTX only)
// ---------------------------------------------------------------------------
__device__ __forceinline__ uint32_t smem_u32(const void* p) {
    uint32_t a;
    asm("{ .reg .u64 t; cvta.to.shared.u64 t, %1; cvt.u32.u64 %0, t; }" : "=r"(a) : "l"(p));
    return a;
}
__device__ __forceinline__ void cp_async16(uint32_t saddr, const void* gaddr) {
    asm volatile("cp.async.cg.shared.global [%0], [%1], 16;" :: "r"(saddr), "l"(gaddr) : "memory");
}
__device__ __forceinline__ void cp_commit() {
    asm volatile("cp.async.commit_group;" ::: "memory");
}
__device__ __forceinline__ void cp_wait1() {
    asm volatile("cp.async.wait_group 1;" ::: "memory");
}
__device__ __forceinline__ void mma_f16(float* d, const uint32_t* a, const uint32_t* b) {
    asm volatile(
        "mma.sync.aligned.m16n8k16.row.col.f32.f16.f16.f32 "
        "{%0,%1,%2,%3}, {%4,%5,%6,%7}, {%8,%9}, {%0,%1,%2,%3};"
        : "+f"(d[0]), "+f"(d[1]), "+f"(d[2]), "+f"(d[3])
        : "r"(a[0]), "r"(a[1]), "r"(a[2]), "r"(a[3]), "r"(b[0]), "r"(b[1]));
}
__device__ __forceinline__ void ldm_x4(uint32_t* r, uint32_t saddr) {
    asm volatile(
        "ldmatrix.sync.aligned.m8n8.x4.shared.b16 {%0,%1,%2,%3}, [%4];"
        : "=r"(r[0]), "=r"(r[1]), "=r"(r[2]), "=r"(r[3]) : "r"(saddr));
}

// ---------------------------------------------------------------------------
// mma.sync fp16 GEMM: C[m][n] = sum_k A[m][k] * B[n][k]  (both K-major, half)
// BM=BN=128, BK=32 (2 k16 steps). 8 warps (2x4), warp tile 64x32.
// SMEM rows padded to 40 halves; ldmatrix.x4 fragment loads (conflict-free:
// 8 rows x 80B stride touch all 32 banks exactly once per 8x8 matrix).
// 3-stage cp.async pipeline, one __syncthreads per iteration, 2 CTAs/SM.
// ---------------------------------------------------------------------------
#define PAD_ROW_H 40
#define TILE_HALF (128 * PAD_ROW_H)          // 5120 halves = 10240 B
#define BUF_HALF  (2 * TILE_HALF)            // A + B per stage (20480 B)
#define N_STAGES 3
#define GEMM_SMEM_BYTES (N_STAGES * BUF_HALF * 2)  // 61440

template <typename TC, bool HAS_BIAS, bool TRANS_OUT>
__global__ __launch_bounds__(256, 2)
void mma_gemm(const __half* __restrict__ A, int lda, long long bsA,
              const __half* __restrict__ B, int ldb, long long bsB,
              TC* __restrict__ C, int ldc, long long bsC,
              const float* __restrict__ bias, float scale, int Kd)
{
    extern __shared__ __half smh[];
    const uint32_t sbase = smem_u32(smh);

    const int tid = threadIdx.x;
    const int wid = tid >> 5;
    const int lane = tid & 31;
    const int warp_m = wid >> 2;     // 0..1
    const int warp_n = wid & 3;      // 0..3
    const int lr = lane >> 2;        // 0..7  (groupID)
    const int lc = lane & 3;         // 0..3  (threadID_in_group)

    A += (long long)blockIdx.z * bsA;
    B += (long long)blockIdx.z * bsB;
    C += (long long)blockIdx.z * bsC;

    const int brow = blockIdx.y * 128;
    const int bcol = blockIdx.x * 128;

    float acc[4][4][4];
#pragma unroll
    for (int mf = 0; mf < 4; mf++)
#pragma unroll
        for (int nf = 0; nf < 4; nf++)
#pragma unroll
            for (int r = 0; r < 4; r++) acc[mf][nf][r] = 0.f;

    const int nch = Kd >> 5;   // chunks of BK=32

    // loader: per chunk, A tile 128x32 halves + B tile 128x32 halves.
    auto load_chunk = [&](int j, int stage) {
        const uint32_t abuf = sbase + (uint32_t)(stage * BUF_HALF) * 2;
        const uint32_t bbuf = abuf + (uint32_t)TILE_HALF * 2;
#pragma unroll
        for (int it = 0; it < 2; it++) {
            int idx = tid + 256 * it;             // 0..511
            int row = idx >> 2, c8 = idx & 3;
            cp_async16(abuf + (uint32_t)(row * (PAD_ROW_H * 2) + c8 * 16),
                       A + (long long)(brow + row) * lda + j * 32 + c8 * 8);
        }
#pragma unroll
        for (int it = 0; it < 2; it++) {
            int idx = tid + 256 * it;             // 0..511
            int row = idx >> 2, c8 = idx & 3;
            cp_async16(bbuf + (uint32_t)(row * (PAD_ROW_H * 2) + c8 * 16),
                       B + (long long)(bcol + row) * ldb + j * 32 + c8 * 8);
        }
    };

    // ldmatrix per-lane addressing (halves, relative to tile base):
    // A (per mf, per ks): matrices {rows0-7,k0-7},{rows8-15,k0-7},
    //                               {rows0-7,k8-15},{rows8-15,k8-15}
    //   lane -> row = warp_m*64 + mf*16 + (lane&15), col = ks*16 + (lane>>4)*8
    // B (per nf-pair, per ks): matrices {nf,k0-7},{nf,k8-15},{nf+1,k0-7},{nf+1,k8-15}
    //   lane -> row = warp_n*32 + nfp*16 + ((lane>>4)<<3) + (lane&7),
    //           col = ks*16 + (((lane>>3)&1)<<3)
    const int a_row_l = warp_m * 64 + (lane & 15);
    const int a_col_l = (lane >> 4) << 3;
    const int b_row_l = warp_n * 32 + ((lane >> 4) << 3) + (lane & 7);
    const int b_col_l = ((lane >> 3) & 1) << 3;

    // prologue: chunks 0, 1 -> stages 0, 1
    load_chunk(0, 0);
    cp_commit();
    load_chunk(1, 1);
    cp_commit();

    int stage_c = 0;
    int stage_l = 2;
    for (int i = 0; i < nch; i++) {
        cp_wait1();          // chunk i resident (this thread)
        __syncthreads();     // publish chunk i; stage_l proven free
        if (i + 2 < nch) load_chunk(i + 2, stage_l);
        cp_commit();         // one group per iteration (possibly empty)

        const uint32_t abuf = sbase + (uint32_t)(stage_c * BUF_HALF) * 2;
        const uint32_t bbuf = abuf + (uint32_t)TILE_HALF * 2;

#pragma unroll
        for (int ks = 0; ks < 2; ks++) {
            const int kbase = ks * 16;
            uint32_t af[4][4];
#pragma unroll
            for (int mf = 0; mf < 4; mf++) {
                uint32_t sa = abuf +
                    (uint32_t)(((a_row_l + mf * 16) * PAD_ROW_H) + kbase + a_col_l) * 2;
                ldm_x4(af[mf], sa);
            }
            uint32_t bf[4][2];
#pragma unroll
            for (int nfp = 0; nfp < 2; nfp++) {
                uint32_t br[4];
                uint32_t sb = bbuf +
                    (uint32_t)(((b_row_l + nfp * 16) * PAD_ROW_H) + kbase + b_col_l) * 2;
                ldm_x4(br, sb);
                bf[2 * nfp][0]     = br[0];
                bf[2 * nfp][1]     = br[1];
                bf[2 * nfp + 1][0] = br[2];
                bf[2 * nfp + 1][1] = br[3];
            }
#pragma unroll
            for (int mf = 0; mf < 4; mf++)
#pragma unroll
                for (int nf = 0; nf < 4; nf++)
                    mma_f16(acc[mf][nf], af[mf], bf[nf]);
        }

        stage_c = (stage_c == 2) ? 0 : stage_c + 1;
        stage_l = (stage_l == 2) ? 0 : stage_l + 1;
    }

    // epilogue: c0/c1 = (lr, 2lc/2lc+1), c2/c3 = (lr+8, same cols)
#pragma unroll
    for (int mf = 0; mf < 4; mf++) {
        int gm0 = brow + warp_m * 64 + mf * 16 + lr;
#pragma unroll
        for (int nf = 0; nf < 4; nf++) {
            int gn = bcol + warp_n * 32 + nf * 8 + 2 * lc;
#pragma unroll
            for (int half_i = 0; half_i < 2; half_i++) {
                int gm = gm0 + half_i * 8;
                float v0 = acc[mf][nf][half_i * 2 + 0];
                float v1 = acc[mf][nf][half_i * 2 + 1];
                if (HAS_BIAS) {
                    v0 = (v0 + bias[gn]) * scale;
                    v1 = (v1 + bias[gn + 1]) * scale;
                }
                if (!TRANS_OUT) {
                    if (sizeof(TC) == 2) {
                        __half2 h = __floats2half2_rn(v0, v1);
                        *reinterpret_cast<__half2*>(
                            reinterpret_cast<__half*>(C) + (long long)gm * ldc + gn) = h;
                    } else {
                        *reinterpret_cast<float2*>(
                            reinterpret_cast<float*>(C) + (long long)gm * ldc + gn) =
                            make_float2(v0, v1);
                    }
                } else {
                    // C = vt[(b*8+h)*512 + d][t] (half), gm=(t*4+b), gn=(h*512+d)
                    int t = gm >> 2, b = gm & 3;
                    int h0 = gn >> 9, d0 = gn & 511;
                    int h1 = (gn + 1) >> 9, d1 = (gn + 1) & 511;
                    __half* Ch = reinterpret_cast<__half*>(C);
                    Ch[((size_t)((b << 3) | h0) * 512 + d0) * 2048 + t] = __float2half_rn(v0);
                    Ch[((size_t)((b << 3) | h1) * 512 + d1) * 2048 + t] = __float2half_rn(v1);
                }
            }
        }
    }
}

// ---------------------------------------------------------------------------
// x (float) -> half
// ---------------------------------------------------------------------------
__global__ __launch_bounds__(256)
void convert_x_kernel(const float* __restrict__ x, __half* __restrict__ xh, int n4)
{
    int i = blockIdx.x * 256 + threadIdx.x;
    if (i < n4) {
        float4 v = reinterpret_cast<const float4*>(x)[i];
        reinterpret_cast<__half2*>(xh)[2 * i]     = __floats2half2_rn(v.x, v.y);
        reinterpret_cast<__half2*>(xh)[2 * i + 1] = __floats2half2_rn(v.z, v.w);
    }
}

// ---------------------------------------------------------------------------
// W (K x F, float) -> Wt (F x K, half).  block (32,8), grid (F/32, K/32)
// ---------------------------------------------------------------------------
__global__ __launch_bounds__(256)
void transpose_half_kernel(const float* __restrict__ W, __half* __restrict__ Wt,
                           int rows, int cols)
{
    __shared__ float tile[32][33];
    int bx = blockIdx.x * 32;   // col base (F)
    int by = blockIdx.y * 32;   // row base (K)
    int tx = threadIdx.x, ty = threadIdx.y;
#pragma unroll
    for (int i = 0; i < 4; i++)
        tile[ty + 8 * i][tx] = W[(size_t)(by + ty + 8 * i) * cols + bx + tx];
    __syncthreads();
#pragma unroll
    for (int i = 0; i < 4; i++)
        Wt[(size_t)(bx + ty + 8 * i) * rows + by + tx] =
            __float2half_rn(tile[tx][ty + 8 * i]);
}

// ---------------------------------------------------------------------------
// Row softmax over 2048 cols: fp32 scores in, fp16 probs out
// ---------------------------------------------------------------------------
__global__ __launch_bounds__(256)
void softmax_rows_kernel(const float* __restrict__ S, __half* __restrict__ P)
{
    const int NC = T_DIM;
    const int PT = NC / 256;
    const float* p = S + (size_t)blockIdx.x * NC;
    __half* q = P + (size_t)blockIdx.x * NC;
    int tid = threadIdx.x;

    float vals[8];
    float vmax = -INFINITY;
#pragma unroll
    for (int i = 0; i < PT; i++) {
        vals[i] = p[tid + i * 256];
        vmax = fmaxf(vmax, vals[i]);
    }
    __shared__ float red[256];
    red[tid] = vmax; __syncthreads();
    for (int s = 128; s > 0; s >>= 1) {
        if (tid < s) red[tid] = fmaxf(red[tid], red[tid + s]);
        __syncthreads();
    }
    vmax = red[0]; __syncthreads();

    float sum = 0.f;
#pragma unroll
    for (int i = 0; i < PT; i++) {
        vals[i] = __expf(vals[i] - vmax);
        sum += vals[i];
    }
    red[tid] = sum; __syncthreads();
    for (int s = 128; s > 0; s >>= 1) {
        if (tid < s) red[tid] += red[tid + s];
        __syncthreads();
    }
    float inv = 1.f / red[0];
#pragma unroll
    for (int i = 0; i < PT; i++) q[tid + i * 256] = __float2half_rn(vals[i] * inv);
}

// ---------------------------------------------------------------------------
// Output projection (fp32): out[row][o] = sum_f ctx[row][f]*Wo[f][o] + bo[o]
// ---------------------------------------------------------------------------
__global__ __launch_bounds__(256)
void out_proj_kernel(const float* __restrict__ ctx, const float* __restrict__ Wo,
                     const float* __restrict__ bo, float* __restrict__ out)
{
    const float* c = ctx + (size_t)blockIdx.x * F_DIM;
    float acc[8] = {0, 0, 0, 0, 0, 0, 0, 0};
    for (int f = threadIdx.x; f < F_DIM; f += 256) {
        float cv = c[f];
        const float4* w = reinterpret_cast<const float4*>(Wo + (size_t)f * H_DIM);
        float4 w0 = w[0], w1 = w[1];
        acc[0] = fmaf(cv, w0.x, acc[0]); acc[1] = fmaf(cv, w0.y, acc[1]);
        acc[2] = fmaf(cv, w0.z, acc[2]); acc[3] = fmaf(cv, w0.w, acc[3]);
        acc[4] = fmaf(cv, w1.x, acc[4]); acc[5] = fmaf(cv, w1.y, acc[5]);
        acc[6] = fmaf(cv, w1.z, acc[6]); acc[7] = fmaf(cv, w1.w, acc[7]);
    }
    __shared__ float red[8][256];
#pragma unroll
    for (int o = 0; o < 8; o++) red[o][threadIdx.x] = acc[o];
    __syncthreads();
    for (int s = 128; s > 0; s >>= 1) {
        if (threadIdx.x < s) {
#pragma unroll
            for (int o = 0; o < 8; o++)
                red[o][threadIdx.x] += red[o][threadIdx.x + s];
        }
        __syncthreads();
    }
    if (threadIdx.x < 8)
        out[(size_t)blockIdx.x * H_DIM + threadIdx.x] = red[threadIdx.x][0] + bo[threadIdx.x];
}

// ---------------------------------------------------------------------------
extern "C" void kernel_launch(void* const* d_in, const int* in_sizes, int n_in,
                              void* d_out, int out_size)
{
    const float* x  = (const float*)d_in[0];
    const float* Wq = (const float*)d_in[1];
    const float* bq = (const float*)d_in[2];
    const float* Wk = (const float*)d_in[3];
    const float* bk = (const float*)d_in[4];
    const float* Wv = (const float*)d_in[5];
    const float* bv = (const float*)d_in[6];
    const float* Wo = (const float*)d_in[7];
    const float* bo = (const float*)d_in[8];
    float* out = (float*)d_out;

    __half *xh, *wtq, *wtk, *wtv, *qh, *kh, *vt, *pp;
    float *s, *ctx;
    cudaGetSymbolAddress((void**)&xh,  g_xh);
    cudaGetSymbolAddress((void**)&wtq, g_wtq);
    cudaGetSymbolAddress((void**)&wtk, g_wtk);
    cudaGetSymbolAddress((void**)&wtv, g_wtv);
    cudaGetSymbolAddress((void**)&qh,  g_qh);
    cudaGetSymbolAddress((void**)&kh,  g_kh);
    cudaGetSymbolAddress((void**)&vt,  g_vt);
    cudaGetSymbolAddress((void**)&s,   g_s);
    cudaGetSymbolAddress((void**)&pp,  g_p);
    cudaGetSymbolAddress((void**)&ctx, g_ctx);

    cudaFuncSetAttribute(mma_gemm<__half, true,  false>,
                         cudaFuncAttributeMaxDynamicSharedMemorySize, GEMM_SMEM_BYTES);
    cudaFuncSetAttribute(mma_gemm<__half, true,  true>,
                         cudaFuncAttributeMaxDynamicSharedMemorySize, GEMM_SMEM_BYTES);
    cudaFuncSetAttribute(mma_gemm<float,  false, false>,
                         cudaFuncAttributeMaxDynamicSharedMemorySize, GEMM_SMEM_BYTES);

    const float scale_qk = powf((float)K_DIM, -0.25f);

    // 0) convert inputs to half
    {
        int n4 = M_ROWS * K_DIM / 4;
        convert_x_kernel<<<(n4 + 255) / 256, 256>>>(x, xh, n4);
        dim3 tg(F_DIM / 32, K_DIM / 32);
        dim3 tb(32, 8);
        transpose_half_kernel<<<tg, tb>>>(Wq, wtq, K_DIM, F_DIM);
        transpose_half_kernel<<<tg, tb>>>(Wk, wtk, K_DIM, F_DIM);
        transpose_half_kernel<<<tg, tb>>>(Wv, wtv, K_DIM, F_DIM);
    }

    // 1) QKV projections: (8192x512)@(512x4096)
    {
        dim3 grid(F_DIM / 128, M_ROWS / 128, 1);  // (32, 64)
        mma_gemm<__half, true, false><<<grid, 256, GEMM_SMEM_BYTES>>>(
            xh, K_DIM, 0, wtq, K_DIM, 0, qh, F_DIM, 0, bq, scale_qk, K_DIM);
        mma_gemm<__half, true, false><<<grid, 256, GEMM_SMEM_BYTES>>>(
            xh, K_DIM, 0, wtk, K_DIM, 0, kh, F_DIM, 0, bk, scale_qk, K_DIM);
        mma_gemm<__half, true, true><<<grid, 256, GEMM_SMEM_BYTES>>>(
            xh, K_DIM, 0, wtv, K_DIM, 0, vt, 0, 0, bv, 1.0f, K_DIM);
    }

    // 2) Scores: per head n, S_n = Q_n @ K_n^T  (2048x2048, K=512), fp32 out
    {
        dim3 grid(T_DIM / 128, T_DIM / 128, N_HEADS);  // (16, 16, 32)
        mma_gemm<float, false, false><<<grid, 256, GEMM_SMEM_BYTES>>>(
            qh, ROWSTRIDE_T, (long long)K_DIM,
            kh, ROWSTRIDE_T, (long long)K_DIM,
            s, T_DIM, (long long)T_DIM * T_DIM,
            nullptr, 1.0f, K_DIM);
    }

    // 3) Softmax: fp32 scores -> fp16 probs
    softmax_rows_kernel<<<N_HEADS * T_DIM, 256>>>(s, pp);

    // 4) Context: per head n, Ctx_n = P_n @ V_n  (2048x512, K=2048), fp32 out
    {
        dim3 grid(K_DIM / 128, T_DIM / 128, N_HEADS);  // (4, 16, 32)
        mma_gemm<float, false, false><<<grid, 256, GEMM_SMEM_BYTES>>>(
            pp, T_DIM, (long long)T_DIM * T_DIM,
            vt, T_DIM, (long long)K_DIM * T_DIM,
            ctx, ROWSTRIDE_T, (long long)K_DIM,
            nullptr, 1.0f, T_DIM);
    }

    // 5) Output projection (fp32, tiny)
    out_proj_kernel<<<M_ROWS, 256>>>(ctx, Wo, bo, out);
}